// round 3
// baseline (speedup 1.0000x reference)
#include <cuda_runtime.h>
#include <cuda_fp16.h>
#include <cstdint>

// ============================================================
// Problem sizes (fixed per reference)
// ============================================================
#define B_S       8192          // GEMM M  (B*S = 4*2048)
#define IN_DIM    4096          // K
#define OUT_DIM   4096          // N
// GEMM tiling
#define CTA_M     128
#define CTA_N     256
#define KC        64                        // K elems per chunk (128B rows)
#define ROW_B     128                       // bytes per smem row
#define NUM_IT    (IN_DIM / KC)             // 64
#define STAGES    3
#define XT_B      (CTA_M * ROW_B)           // 16384 per x tile
#define WT_B      (CTA_N * ROW_B)           // 32768
#define STAGE_B   (2 * XT_B + WT_B)         // 65536 (xh, xl, w)
#define SMEM_BYTES (STAGES * STAGE_B)       // 196608

// ============================================================
// Scratch (device globals; no runtime allocation allowed)
// ============================================================
__device__ __align__(16) __half g_xh[(size_t)B_S * IN_DIM];
__device__ __align__(16) __half g_xl[(size_t)B_S * IN_DIM];
__device__ __align__(16) __half g_w [(size_t)OUT_DIM * IN_DIM];

// ============================================================
// PTX helpers (compute_100-safe: mma.sync / ldmatrix / cp.async only)
// ============================================================
static __device__ __forceinline__ void ldsm_x4(uint32_t* r, uint32_t addr) {
    asm volatile("ldmatrix.sync.aligned.m8n8.x4.shared.b16 {%0,%1,%2,%3}, [%4];"
        : "=r"(r[0]), "=r"(r[1]), "=r"(r[2]), "=r"(r[3]) : "r"(addr));
}

static __device__ __forceinline__ void mma16816(float* d, const uint32_t* a,
                                                const uint32_t* b) {
    asm volatile(
        "mma.sync.aligned.m16n8k16.row.col.f32.f16.f16.f32 "
        "{%0,%1,%2,%3}, {%4,%5,%6,%7}, {%8,%9}, {%0,%1,%2,%3};"
        : "+f"(d[0]), "+f"(d[1]), "+f"(d[2]), "+f"(d[3])
        : "r"(a[0]), "r"(a[1]), "r"(a[2]), "r"(a[3]), "r"(b[0]), "r"(b[1]));
}

#define CP_ASYNC16(dst, src) \
    asm volatile("cp.async.cg.shared.global [%0], [%1], 16;" :: "r"(dst), "l"(src))
#define CP_COMMIT() asm volatile("cp.async.commit_group;" ::: "memory")
#define CP_WAIT1()  asm volatile("cp.async.wait_group 1;" ::: "memory")
#define CP_WAIT0()  asm volatile("cp.async.wait_group 0;" ::: "memory")

// swizzled byte offset within a tile: row r (128B rows), 16B chunk c (0..7)
static __device__ __forceinline__ uint32_t sw(uint32_t r, uint32_t c) {
    return r * ROW_B + ((c ^ (r & 7u)) << 4);
}

// ============================================================
// Prep kernel 1: split x (fp32) into fp16 hi + fp16 residual
// ============================================================
__global__ void split_x_kernel(const float4* __restrict__ x) {
    int i = blockIdx.x * blockDim.x + threadIdx.x;   // covers B_S*IN_DIM/4
    float4 v = x[i];
    float f[4] = {v.x, v.y, v.z, v.w};
    union U { __half h[4]; uint2 u; };
    U H, L;
#pragma unroll
    for (int q = 0; q < 4; ++q) {
        __half hb = __float2half_rn(f[q]);
        H.h[q] = hb;
        L.h[q] = __float2half_rn(f[q] - __half2float(hb));
    }
    reinterpret_cast<uint2*>(g_xh)[i] = H.u;
    reinterpret_cast<uint2*>(g_xl)[i] = L.u;
}

// ============================================================
// Prep kernel 2: dequantize W from codes into fp16
// ============================================================
__global__ void dequant_w_kernel(const int4* __restrict__ codes,
                                 const float* __restrict__ qgrid) {
    int i = blockIdx.x * blockDim.x + threadIdx.x;   // covers OUT*IN/4
    int4 c = codes[i];
    int o = i >> 10;                  // (4*i) / 4096 : output row
    const float* g = qgrid + o * 8;   // GROUPS=1, GRID=8
    union U { __half h[4]; uint2 u; };
    U H;
    H.h[0] = __float2half_rn(g[c.x]);
    H.h[1] = __float2half_rn(g[c.y]);
    H.h[2] = __float2half_rn(g[c.z]);
    H.h[3] = __float2half_rn(g[c.w]);
    reinterpret_cast<uint2*>(g_w)[i] = H.u;
}

// ============================================================
// GEMM: out[8192,4096] = xh @ w^T + xl @ w^T   (fp16 in, fp32 acc)
// CTA 128x256, 8 warps (2 along M x 4 along N), warp tile 64x64.
// 3-stage cp.async pipeline, K chunk 64.
// ============================================================
__global__ void __launch_bounds__(256, 1)
gemm_kernel(float* __restrict__ out)
{
    extern __shared__ char dsm[];
    const uint32_t smem = (uint32_t)__cvta_generic_to_shared(dsm);
    const int tid  = threadIdx.x;
    const int wid  = tid >> 5;
    const int lane = tid & 31;
    const int m0 = blockIdx.y * CTA_M;
    const int n0 = blockIdx.x * CTA_N;
    const int warp_m = wid >> 2;          // 0..1 -> M offset *64
    const int warp_n = wid & 3;           // 0..3 -> N offset *64

    // ---------------- async load machinery ----------------
    // per stage: [0, XT_B)  xh tile (128 x 128B)
    //            [XT_B, 2*XT_B) xl
    //            [2*XT_B, STAGE_B) w (256 x 128B)
    auto load_chunk = [&](int it) {
        const uint32_t sb = smem + (uint32_t)(it % STAGES) * STAGE_B;
        const int k0 = it * KC;
        // xh: 1024 16B-chunks, 4 per thread
#pragma unroll
        for (int j = 0; j < 4; ++j) {
            int id = tid + 256 * j;        // 0..1023
            uint32_t r = id >> 3, c = id & 7;
            const char* gp = reinterpret_cast<const char*>(
                g_xh + (size_t)(m0 + r) * IN_DIM + k0) + c * 16;
            CP_ASYNC16(sb + sw(r, c), gp);
        }
        // xl
#pragma unroll
        for (int j = 0; j < 4; ++j) {
            int id = tid + 256 * j;
            uint32_t r = id >> 3, c = id & 7;
            const char* gp = reinterpret_cast<const char*>(
                g_xl + (size_t)(m0 + r) * IN_DIM + k0) + c * 16;
            CP_ASYNC16(sb + XT_B + sw(r, c), gp);
        }
        // w: 2048 chunks, 8 per thread
#pragma unroll
        for (int j = 0; j < 8; ++j) {
            int id = tid + 256 * j;        // 0..2047
            uint32_t r = id >> 3, c = id & 7;
            const char* gp = reinterpret_cast<const char*>(
                g_w + (size_t)(n0 + r) * IN_DIM + k0) + c * 16;
            CP_ASYNC16(sb + 2 * XT_B + sw(r, c), gp);
        }
        CP_COMMIT();
    };

    float acc[4][8][4];
#pragma unroll
    for (int a = 0; a < 4; ++a)
#pragma unroll
        for (int b = 0; b < 8; ++b)
#pragma unroll
            for (int q = 0; q < 4; ++q) acc[a][b][q] = 0.f;

    // per-thread ldmatrix row/col components (x4 pattern)
    const uint32_t lrow = lane & 15;          // row within 16-row block
    const uint32_t lcol = lane >> 4;          // 0/1 -> +8 halves (16B col)
    const uint32_t arow = warp_m * 64 + lrow; // xh/xl tile row
    const uint32_t brow_base = warp_n * 64 + lrow;

    load_chunk(0);
    load_chunk(1);

    for (int it = 0; it < NUM_IT; ++it) {
        if (it < NUM_IT - 1) CP_WAIT1(); else CP_WAIT0();
        __syncthreads();
        if (it + 2 < NUM_IT) load_chunk(it + 2);

        const uint32_t sb = smem + (uint32_t)(it % STAGES) * STAGE_B;
        const uint32_t sxh = sb;
        const uint32_t sxl = sb + XT_B;
        const uint32_t swt = sb + 2 * XT_B;

#pragma unroll
        for (int ks = 0; ks < 4; ++ks) {        // 4 x k16 per chunk
            const uint32_t cc = (uint32_t)(2 * ks) + lcol;   // 16B col index
            // B frags: 4 x ldmatrix.x4 covering 8 n8-tiles
            uint32_t Bf[8][2];
#pragma unroll
            for (int np = 0; np < 4; ++np) {
                uint32_t r4[4];
                ldsm_x4(r4, swt + sw(brow_base + np * 16, cc));
                Bf[2 * np    ][0] = r4[0]; Bf[2 * np    ][1] = r4[2];
                Bf[2 * np + 1][0] = r4[1]; Bf[2 * np + 1][1] = r4[3];
            }
#pragma unroll
            for (int mt = 0; mt < 4; ++mt) {
                uint32_t Ah[4], Al[4];
                ldsm_x4(Ah, sxh + sw(arow + mt * 16, cc));
                ldsm_x4(Al, sxl + sw(arow + mt * 16, cc));
#pragma unroll
                for (int nt = 0; nt < 8; ++nt)
                    mma16816(acc[mt][nt], Ah, Bf[nt]);
#pragma unroll
                for (int nt = 0; nt < 8; ++nt)
                    mma16816(acc[mt][nt], Al, Bf[nt]);
            }
        }
    }

    // ---------------- epilogue: direct fp32 stores ----------------
    const int orow = m0 + warp_m * 64 + (lane >> 2);
    const int ocol = n0 + warp_n * 64 + (lane & 3) * 2;
#pragma unroll
    for (int mt = 0; mt < 4; ++mt) {
#pragma unroll
        for (int nt = 0; nt < 8; ++nt) {
            float* p0 = out + (size_t)(orow + mt * 16) * OUT_DIM + ocol + nt * 8;
            float* p1 = out + (size_t)(orow + mt * 16 + 8) * OUT_DIM + ocol + nt * 8;
            float2 v0 = make_float2(acc[mt][nt][0], acc[mt][nt][1]);
            float2 v1 = make_float2(acc[mt][nt][2], acc[mt][nt][3]);
            *reinterpret_cast<float2*>(p0) = v0;
            *reinterpret_cast<float2*>(p1) = v1;
        }
    }
}

// ============================================================
// Launch
// ============================================================
extern "C" void kernel_launch(void* const* d_in, const int* in_sizes, int n_in,
                              void* d_out, int out_size) {
    // Identify inputs by element count:
    //   x: 33554432 fp32, quant_grid: 32768 fp32, weight_codes: 16777216 int32
    const float* x = nullptr;
    const float* qgrid = nullptr;
    const int* codes = nullptr;
    for (int i = 0; i < n_in; ++i) {
        if (in_sizes[i] == 33554432)      x = (const float*)d_in[i];
        else if (in_sizes[i] == 32768)    qgrid = (const float*)d_in[i];
        else if (in_sizes[i] == 16777216) codes = (const int*)d_in[i];
    }
    float* out = (float*)d_out;

    split_x_kernel<<<(B_S * IN_DIM / 4) / 256, 256>>>(
        reinterpret_cast<const float4*>(x));
    dequant_w_kernel<<<(OUT_DIM * IN_DIM / 4) / 256, 256>>>(
        reinterpret_cast<const int4*>(codes), qgrid);

    cudaFuncSetAttribute(gemm_kernel,
                         cudaFuncAttributeMaxDynamicSharedMemorySize, SMEM_BYTES);
    dim3 grid(OUT_DIM / CTA_N, B_S / CTA_M);   // x = N blocks (fast), y = M
    gemm_kernel<<<grid, 256, SMEM_BYTES>>>(out);
}

// round 4
// speedup vs baseline: 1.8102x; 1.8102x over previous
#include <cuda_runtime.h>
#include <cuda_fp16.h>
#include <cstdint>

// ============================================================
// Problem sizes (fixed per reference)
// ============================================================
#define B_S       8192          // GEMM M  (B*S = 4*2048)
#define IN_DIM    4096          // K
#define OUT_DIM   4096          // N
// GEMM tiling
#define CTA_M     128
#define CTA_N     256
#define KC        64                        // K elems per chunk (128B rows)
#define ROW_B     128                       // bytes per smem row
#define NUM_IT    (IN_DIM / KC)             // 64
#define STAGES    4
#define XT_B      (CTA_M * ROW_B)           // 16384 (x tile)
#define WT_B      (CTA_N * ROW_B)           // 32768 (w tile)
#define STAGE_B   (XT_B + WT_B)             // 49152
#define SMEM_BYTES (STAGES * STAGE_B)       // 196608

// ============================================================
// Scratch (device globals; no runtime allocation allowed)
// ============================================================
__device__ __align__(16) __half g_x[(size_t)B_S * IN_DIM];
__device__ __align__(16) __half g_w[(size_t)OUT_DIM * IN_DIM];

// ============================================================
// PTX helpers (compute_100-safe: mma.sync / ldmatrix / cp.async only)
// ============================================================
static __device__ __forceinline__ void ldsm_x4(uint32_t* r, uint32_t addr) {
    asm volatile("ldmatrix.sync.aligned.m8n8.x4.shared.b16 {%0,%1,%2,%3}, [%4];"
        : "=r"(r[0]), "=r"(r[1]), "=r"(r[2]), "=r"(r[3]) : "r"(addr));
}

static __device__ __forceinline__ void mma16816(float* d, const uint32_t* a,
                                                const uint32_t* b) {
    asm volatile(
        "mma.sync.aligned.m16n8k16.row.col.f32.f16.f16.f32 "
        "{%0,%1,%2,%3}, {%4,%5,%6,%7}, {%8,%9}, {%0,%1,%2,%3};"
        : "+f"(d[0]), "+f"(d[1]), "+f"(d[2]), "+f"(d[3])
        : "r"(a[0]), "r"(a[1]), "r"(a[2]), "r"(a[3]), "r"(b[0]), "r"(b[1]));
}

#define CP_ASYNC16(dst, src) \
    asm volatile("cp.async.cg.shared.global [%0], [%1], 16;" :: "r"(dst), "l"(src))
#define CP_COMMIT() asm volatile("cp.async.commit_group;" ::: "memory")
#define CP_WAIT2()  asm volatile("cp.async.wait_group 2;" ::: "memory")
#define CP_WAIT0()  asm volatile("cp.async.wait_group 0;" ::: "memory")

// swizzled byte offset within a tile: row r (128B rows), 16B chunk c (0..7)
static __device__ __forceinline__ uint32_t sw(uint32_t r, uint32_t c) {
    return r * ROW_B + ((c ^ (r & 7u)) << 4);
}

// ============================================================
// Prep kernel 1: convert x (fp32) to fp16
// ============================================================
__global__ void conv_x_kernel(const float4* __restrict__ x) {
    int i = blockIdx.x * blockDim.x + threadIdx.x;   // covers B_S*IN_DIM/4
    float4 v = x[i];
    union U { __half h[4]; uint2 u; };
    U H;
    H.h[0] = __float2half_rn(v.x);
    H.h[1] = __float2half_rn(v.y);
    H.h[2] = __float2half_rn(v.z);
    H.h[3] = __float2half_rn(v.w);
    reinterpret_cast<uint2*>(g_x)[i] = H.u;
}

// ============================================================
// Prep kernel 2: dequantize W from codes into fp16
// ============================================================
__global__ void dequant_w_kernel(const int4* __restrict__ codes,
                                 const float* __restrict__ qgrid) {
    int i = blockIdx.x * blockDim.x + threadIdx.x;   // covers OUT*IN/4
    int4 c = codes[i];
    int o = i >> 10;                  // (4*i) / 4096 : output row
    const float* g = qgrid + o * 8;   // GROUPS=1, GRID=8
    union U { __half h[4]; uint2 u; };
    U H;
    H.h[0] = __float2half_rn(g[c.x]);
    H.h[1] = __float2half_rn(g[c.y]);
    H.h[2] = __float2half_rn(g[c.z]);
    H.h[3] = __float2half_rn(g[c.w]);
    reinterpret_cast<uint2*>(g_w)[i] = H.u;
}

// ============================================================
// GEMM: out[8192,4096] = x @ w^T   (fp16 in, fp32 acc)
// CTA 128x256, 8 warps (2 along M x 4 along N), warp tile 64x64.
// 4-stage cp.async pipeline, K chunk 64.
// ============================================================
__global__ void __launch_bounds__(256, 1)
gemm_kernel(float* __restrict__ out)
{
    extern __shared__ char dsm[];
    const uint32_t smem = (uint32_t)__cvta_generic_to_shared(dsm);
    const int tid  = threadIdx.x;
    const int wid  = tid >> 5;
    const int lane = tid & 31;
    const int m0 = blockIdx.y * CTA_M;
    const int n0 = blockIdx.x * CTA_N;
    const int warp_m = wid >> 2;          // 0..1 -> M offset *64
    const int warp_n = wid & 3;           // 0..3 -> N offset *64

    // ---------------- async load machinery ----------------
    // per stage: [0, XT_B) x tile (128 x 128B), [XT_B, STAGE_B) w (256 x 128B)
    auto load_chunk = [&](int it) {
        const uint32_t sb = smem + (uint32_t)(it & (STAGES - 1)) * STAGE_B;
        const int k0 = it * KC;
        // x: 1024 16B-chunks, 4 per thread
#pragma unroll
        for (int j = 0; j < 4; ++j) {
            int id = tid + 256 * j;        // 0..1023
            uint32_t r = id >> 3, c = id & 7;
            const char* gp = reinterpret_cast<const char*>(
                g_x + (size_t)(m0 + r) * IN_DIM + k0) + c * 16;
            CP_ASYNC16(sb + sw(r, c), gp);
        }
        // w: 2048 chunks, 8 per thread
#pragma unroll
        for (int j = 0; j < 8; ++j) {
            int id = tid + 256 * j;        // 0..2047
            uint32_t r = id >> 3, c = id & 7;
            const char* gp = reinterpret_cast<const char*>(
                g_w + (size_t)(n0 + r) * IN_DIM + k0) + c * 16;
            CP_ASYNC16(sb + XT_B + sw(r, c), gp);
        }
        CP_COMMIT();
    };

    float acc[4][8][4];
#pragma unroll
    for (int a = 0; a < 4; ++a)
#pragma unroll
        for (int b = 0; b < 8; ++b)
#pragma unroll
            for (int q = 0; q < 4; ++q) acc[a][b][q] = 0.f;

    // per-thread ldmatrix row/col components (x4 pattern)
    const uint32_t lrow = lane & 15;          // row within 16-row block
    const uint32_t lcol = lane >> 4;          // 0/1 -> +8 halves (16B col)
    const uint32_t arow = warp_m * 64 + lrow; // x tile row
    const uint32_t brow_base = warp_n * 64 + lrow;

    load_chunk(0);
    load_chunk(1);
    load_chunk(2);

    for (int it = 0; it < NUM_IT; ++it) {
        if (it < NUM_IT - 3) CP_WAIT2(); else CP_WAIT0();
        __syncthreads();
        if (it + 3 < NUM_IT) load_chunk(it + 3);

        const uint32_t sb = smem + (uint32_t)(it & (STAGES - 1)) * STAGE_B;
        const uint32_t sx = sb;
        const uint32_t swt = sb + XT_B;

#pragma unroll
        for (int ks = 0; ks < 4; ++ks) {        // 4 x k16 per chunk
            const uint32_t cc = (uint32_t)(2 * ks) + lcol;   // 16B col index
            // B frags: 4 x ldmatrix.x4 covering 8 n8-tiles
            uint32_t Bf[8][2];
#pragma unroll
            for (int np = 0; np < 4; ++np) {
                uint32_t r4[4];
                ldsm_x4(r4, swt + sw(brow_base + np * 16, cc));
                Bf[2 * np    ][0] = r4[0]; Bf[2 * np    ][1] = r4[2];
                Bf[2 * np + 1][0] = r4[1]; Bf[2 * np + 1][1] = r4[3];
            }
#pragma unroll
            for (int mt = 0; mt < 4; ++mt) {
                uint32_t Af[4];
                ldsm_x4(Af, sx + sw(arow + mt * 16, cc));
#pragma unroll
                for (int nt = 0; nt < 8; ++nt)
                    mma16816(acc[mt][nt], Af, Bf[nt]);
            }
        }
    }

    // ---------------- epilogue: direct fp32 stores ----------------
    const int orow = m0 + warp_m * 64 + (lane >> 2);
    const int ocol = n0 + warp_n * 64 + (lane & 3) * 2;
#pragma unroll
    for (int mt = 0; mt < 4; ++mt) {
#pragma unroll
        for (int nt = 0; nt < 8; ++nt) {
            float* p0 = out + (size_t)(orow + mt * 16) * OUT_DIM + ocol + nt * 8;
            float* p1 = out + (size_t)(orow + mt * 16 + 8) * OUT_DIM + ocol + nt * 8;
            *reinterpret_cast<float2*>(p0) =
                make_float2(acc[mt][nt][0], acc[mt][nt][1]);
            *reinterpret_cast<float2*>(p1) =
                make_float2(acc[mt][nt][2], acc[mt][nt][3]);
        }
    }
}

// ============================================================
// Launch
// ============================================================
extern "C" void kernel_launch(void* const* d_in, const int* in_sizes, int n_in,
                              void* d_out, int out_size) {
    // Identify inputs by element count:
    //   x: 33554432 fp32, quant_grid: 32768 fp32, weight_codes: 16777216 int32
    const float* x = nullptr;
    const float* qgrid = nullptr;
    const int* codes = nullptr;
    for (int i = 0; i < n_in; ++i) {
        if (in_sizes[i] == 33554432)      x = (const float*)d_in[i];
        else if (in_sizes[i] == 32768)    qgrid = (const float*)d_in[i];
        else if (in_sizes[i] == 16777216) codes = (const int*)d_in[i];
    }
    float* out = (float*)d_out;

    conv_x_kernel<<<(B_S * IN_DIM / 4) / 256, 256>>>(
        reinterpret_cast<const float4*>(x));
    dequant_w_kernel<<<(OUT_DIM * IN_DIM / 4) / 256, 256>>>(
        reinterpret_cast<const int4*>(codes), qgrid);

    cudaFuncSetAttribute(gemm_kernel,
                         cudaFuncAttributeMaxDynamicSharedMemorySize, SMEM_BYTES);
    dim3 grid(OUT_DIM / CTA_N, B_S / CTA_M);   // x = N blocks (fast), y = M
    gemm_kernel<<<grid, 256, SMEM_BYTES>>>(out);
}

// round 5
// speedup vs baseline: 1.8358x; 1.0141x over previous
#include <cuda_runtime.h>
#include <cuda_fp16.h>
#include <cstdint>

// ============================================================
// Problem sizes (fixed per reference)
// ============================================================
#define B_S       8192          // GEMM M  (B*S = 4*2048)
#define IN_DIM    4096          // K
#define OUT_DIM   4096          // N
// GEMM tiling
#define CTA_M     128
#define CTA_N     128
#define KC        64                        // K elems per chunk (128B rows)
#define ROW_B     128                       // bytes per smem row
#define NUM_IT    (IN_DIM / KC)             // 64
#define STAGES    3
#define XT_B      (CTA_M * ROW_B)           // 16384 (x tile)
#define WT_B      (CTA_N * ROW_B)           // 16384 (w tile)
#define STAGE_B   (XT_B + WT_B)             // 32768
#define SMEM_BYTES (STAGES * STAGE_B)       // 98304 per CTA -> 2 CTAs/SM

// ============================================================
// Scratch (device globals; no runtime allocation allowed)
// ============================================================
__device__ __align__(16) __half g_x[(size_t)B_S * IN_DIM];
__device__ __align__(16) __half g_w[(size_t)OUT_DIM * IN_DIM];

// ============================================================
// PTX helpers (compute_100-safe: mma.sync / ldmatrix / cp.async only)
// ============================================================
static __device__ __forceinline__ void ldsm_x4(uint32_t* r, uint32_t addr) {
    asm volatile("ldmatrix.sync.aligned.m8n8.x4.shared.b16 {%0,%1,%2,%3}, [%4];"
        : "=r"(r[0]), "=r"(r[1]), "=r"(r[2]), "=r"(r[3]) : "r"(addr));
}

static __device__ __forceinline__ void mma16816(float* d, const uint32_t* a,
                                                const uint32_t* b) {
    asm volatile(
        "mma.sync.aligned.m16n8k16.row.col.f32.f16.f16.f32 "
        "{%0,%1,%2,%3}, {%4,%5,%6,%7}, {%8,%9}, {%0,%1,%2,%3};"
        : "+f"(d[0]), "+f"(d[1]), "+f"(d[2]), "+f"(d[3])
        : "r"(a[0]), "r"(a[1]), "r"(a[2]), "r"(a[3]), "r"(b[0]), "r"(b[1]));
}

#define CP_ASYNC16(dst, src) \
    asm volatile("cp.async.cg.shared.global [%0], [%1], 16;" :: "r"(dst), "l"(src))
#define CP_COMMIT() asm volatile("cp.async.commit_group;" ::: "memory")
#define CP_WAIT1()  asm volatile("cp.async.wait_group 1;" ::: "memory")
#define CP_WAIT0()  asm volatile("cp.async.wait_group 0;" ::: "memory")

// swizzled byte offset within a tile: row r (128B rows), 16B chunk c (0..7)
static __device__ __forceinline__ uint32_t sw(uint32_t r, uint32_t c) {
    return r * ROW_B + ((c ^ (r & 7u)) << 4);
}

// ============================================================
// Prep kernel 1: convert x (fp32) to fp16
// ============================================================
__global__ void conv_x_kernel(const float4* __restrict__ x) {
    int i = blockIdx.x * blockDim.x + threadIdx.x;   // covers B_S*IN_DIM/4
    float4 v = x[i];
    union U { __half h[4]; uint2 u; };
    U H;
    H.h[0] = __float2half_rn(v.x);
    H.h[1] = __float2half_rn(v.y);
    H.h[2] = __float2half_rn(v.z);
    H.h[3] = __float2half_rn(v.w);
    reinterpret_cast<uint2*>(g_x)[i] = H.u;
}

// ============================================================
// Prep kernel 2: dequantize W from codes into fp16
// ============================================================
__global__ void dequant_w_kernel(const int4* __restrict__ codes,
                                 const float* __restrict__ qgrid) {
    int i = blockIdx.x * blockDim.x + threadIdx.x;   // covers OUT*IN/4
    int4 c = codes[i];
    int o = i >> 10;                  // (4*i) / 4096 : output row
    const float* g = qgrid + o * 8;   // GROUPS=1, GRID=8
    union U { __half h[4]; uint2 u; };
    U H;
    H.h[0] = __float2half_rn(g[c.x]);
    H.h[1] = __float2half_rn(g[c.y]);
    H.h[2] = __float2half_rn(g[c.z]);
    H.h[3] = __float2half_rn(g[c.w]);
    reinterpret_cast<uint2*>(g_w)[i] = H.u;
}

// ============================================================
// GEMM: out[8192,4096] = x @ w^T   (fp16 in, fp32 acc)
// CTA 128x128, 8 warps (2 along M x 4 along N), warp tile 64x32.
// 3-stage cp.async pipeline, K chunk 64, 2 CTAs per SM.
// ============================================================
__global__ void __launch_bounds__(256, 2)
gemm_kernel(float* __restrict__ out)
{
    extern __shared__ char dsm[];
    const uint32_t smem = (uint32_t)__cvta_generic_to_shared(dsm);
    const int tid  = threadIdx.x;
    const int wid  = tid >> 5;
    const int lane = tid & 31;
    const int m0 = blockIdx.y * CTA_M;
    const int n0 = blockIdx.x * CTA_N;
    const int warp_m = wid >> 2;          // 0..1 -> M offset *64
    const int warp_n = wid & 3;           // 0..3 -> N offset *32

    // ---------------- async load machinery ----------------
    // per stage: [0, XT_B) x tile (128 x 128B), [XT_B, STAGE_B) w (128 x 128B)
    auto load_chunk = [&](int it) {
        const uint32_t sb = smem + (uint32_t)(it % STAGES) * STAGE_B;
        const int k0 = it * KC;
        // x: 1024 16B-chunks, 4 per thread
#pragma unroll
        for (int j = 0; j < 4; ++j) {
            int id = tid + 256 * j;        // 0..1023
            uint32_t r = id >> 3, c = id & 7;
            const char* gp = reinterpret_cast<const char*>(
                g_x + (size_t)(m0 + r) * IN_DIM + k0) + c * 16;
            CP_ASYNC16(sb + sw(r, c), gp);
        }
        // w: 1024 chunks, 4 per thread
#pragma unroll
        for (int j = 0; j < 4; ++j) {
            int id = tid + 256 * j;
            uint32_t r = id >> 3, c = id & 7;
            const char* gp = reinterpret_cast<const char*>(
                g_w + (size_t)(n0 + r) * IN_DIM + k0) + c * 16;
            CP_ASYNC16(sb + XT_B + sw(r, c), gp);
        }
        CP_COMMIT();
    };

    float acc[4][4][4];
#pragma unroll
    for (int a = 0; a < 4; ++a)
#pragma unroll
        for (int b = 0; b < 4; ++b)
#pragma unroll
            for (int q = 0; q < 4; ++q) acc[a][b][q] = 0.f;

    // per-thread ldmatrix row/col components (x4 pattern)
    const uint32_t lrow = lane & 15;          // row within 16-row block
    const uint32_t lcol = lane >> 4;          // 0/1 -> +8 halves (16B col)
    const uint32_t arow = warp_m * 64 + lrow; // x tile row
    const uint32_t brow_base = warp_n * 32 + lrow;

    load_chunk(0);
    load_chunk(1);

    for (int it = 0; it < NUM_IT; ++it) {
        if (it < NUM_IT - 1) CP_WAIT1(); else CP_WAIT0();
        __syncthreads();
        if (it + 2 < NUM_IT) load_chunk(it + 2);

        const uint32_t sb = smem + (uint32_t)(it % STAGES) * STAGE_B;
        const uint32_t sx = sb;
        const uint32_t swt = sb + XT_B;

#pragma unroll
        for (int ks = 0; ks < 4; ++ks) {        // 4 x k16 per chunk
            const uint32_t cc = (uint32_t)(2 * ks) + lcol;   // 16B col index
            // B frags: 2 x ldmatrix.x4 covering 4 n8-tiles
            uint32_t Bf[4][2];
#pragma unroll
            for (int np = 0; np < 2; ++np) {
                uint32_t r4[4];
                ldsm_x4(r4, swt + sw(brow_base + np * 16, cc));
                Bf[2 * np    ][0] = r4[0]; Bf[2 * np    ][1] = r4[2];
                Bf[2 * np + 1][0] = r4[1]; Bf[2 * np + 1][1] = r4[3];
            }
#pragma unroll
            for (int mt = 0; mt < 4; ++mt) {
                uint32_t Af[4];
                ldsm_x4(Af, sx + sw(arow + mt * 16, cc));
#pragma unroll
                for (int nt = 0; nt < 4; ++nt)
                    mma16816(acc[mt][nt], Af, Bf[nt]);
            }
        }
    }

    // ---------------- epilogue: direct fp32 stores ----------------
    const int orow = m0 + warp_m * 64 + (lane >> 2);
    const int ocol = n0 + warp_n * 32 + (lane & 3) * 2;
#pragma unroll
    for (int mt = 0; mt < 4; ++mt) {
#pragma unroll
        for (int nt = 0; nt < 4; ++nt) {
            float* p0 = out + (size_t)(orow + mt * 16) * OUT_DIM + ocol + nt * 8;
            float* p1 = out + (size_t)(orow + mt * 16 + 8) * OUT_DIM + ocol + nt * 8;
            *reinterpret_cast<float2*>(p0) =
                make_float2(acc[mt][nt][0], acc[mt][nt][1]);
            *reinterpret_cast<float2*>(p1) =
                make_float2(acc[mt][nt][2], acc[mt][nt][3]);
        }
    }
}

// ============================================================
// Launch
// ============================================================
extern "C" void kernel_launch(void* const* d_in, const int* in_sizes, int n_in,
                              void* d_out, int out_size) {
    // Identify inputs by element count:
    //   x: 33554432 fp32, quant_grid: 32768 fp32, weight_codes: 16777216 int32
    const float* x = nullptr;
    const float* qgrid = nullptr;
    const int* codes = nullptr;
    for (int i = 0; i < n_in; ++i) {
        if (in_sizes[i] == 33554432)      x = (const float*)d_in[i];
        else if (in_sizes[i] == 32768)    qgrid = (const float*)d_in[i];
        else if (in_sizes[i] == 16777216) codes = (const int*)d_in[i];
    }
    float* out = (float*)d_out;

    conv_x_kernel<<<(B_S * IN_DIM / 4) / 256, 256>>>(
        reinterpret_cast<const float4*>(x));
    dequant_w_kernel<<<(OUT_DIM * IN_DIM / 4) / 256, 256>>>(
        reinterpret_cast<const int4*>(codes), qgrid);

    cudaFuncSetAttribute(gemm_kernel,
                         cudaFuncAttributeMaxDynamicSharedMemorySize, SMEM_BYTES);
    dim3 grid(OUT_DIM / CTA_N, B_S / CTA_M);   // x = N blocks (fast), y = M
    gemm_kernel<<<grid, 256, SMEM_BYTES>>>(out);
}

// round 6
// speedup vs baseline: 1.8948x; 1.0321x over previous
#include <cuda_runtime.h>
#include <cuda_fp16.h>
#include <cstdint>

// ============================================================
// Problem sizes (fixed per reference)
// ============================================================
#define B_S       8192          // GEMM M  (B*S = 4*2048)
#define IN_DIM    4096          // K
#define OUT_DIM   4096          // N
// GEMM tiling: CTA 128x128, 4 warps, warp tile 64x64
#define CTA_M     128
#define CTA_N     128
#define KC        64                        // K elems per chunk (128B rows)
#define ROW_B     128                       // bytes per smem row
#define NUM_IT    (IN_DIM / KC)             // 64
#define STAGES    3
#define XT_B      (CTA_M * ROW_B)           // 16384 (x tile)
#define WT_B      (CTA_N * ROW_B)           // 16384 (w tile)
#define STAGE_B   (XT_B + WT_B)             // 32768
#define SMEM_BYTES (STAGES * STAGE_B)       // 98304 per CTA -> 2 CTAs/SM
#define NTHREADS  128

// ============================================================
// Scratch (device globals; no runtime allocation allowed)
// ============================================================
__device__ __align__(16) __half g_x[(size_t)B_S * IN_DIM];
__device__ __align__(16) __half g_w[(size_t)OUT_DIM * IN_DIM];

// ============================================================
// PTX helpers (compute_100-safe: mma.sync / ldmatrix / cp.async only)
// ============================================================
static __device__ __forceinline__ void ldsm_x4(uint32_t* r, uint32_t addr) {
    asm volatile("ldmatrix.sync.aligned.m8n8.x4.shared.b16 {%0,%1,%2,%3}, [%4];"
        : "=r"(r[0]), "=r"(r[1]), "=r"(r[2]), "=r"(r[3]) : "r"(addr));
}

static __device__ __forceinline__ void mma16816(float* d, const uint32_t* a,
                                                const uint32_t* b) {
    asm volatile(
        "mma.sync.aligned.m16n8k16.row.col.f32.f16.f16.f32 "
        "{%0,%1,%2,%3}, {%4,%5,%6,%7}, {%8,%9}, {%0,%1,%2,%3};"
        : "+f"(d[0]), "+f"(d[1]), "+f"(d[2]), "+f"(d[3])
        : "r"(a[0]), "r"(a[1]), "r"(a[2]), "r"(a[3]), "r"(b[0]), "r"(b[1]));
}

#define CP_ASYNC16(dst, src) \
    asm volatile("cp.async.cg.shared.global [%0], [%1], 16;" :: "r"(dst), "l"(src))
#define CP_COMMIT() asm volatile("cp.async.commit_group;" ::: "memory")
#define CP_WAIT1()  asm volatile("cp.async.wait_group 1;" ::: "memory")
#define CP_WAIT0()  asm volatile("cp.async.wait_group 0;" ::: "memory")

// swizzled byte offset within a tile: row r (128B rows), 16B chunk c (0..7)
static __device__ __forceinline__ uint32_t sw(uint32_t r, uint32_t c) {
    return r * ROW_B + ((c ^ (r & 7u)) << 4);
}

// ============================================================
// Fused prep: blocks [0, 8192) convert x fp32->fp16,
//             blocks [8192, 12288) dequantize w codes->fp16
// ============================================================
#define X_BLOCKS 8192
#define W_BLOCKS 4096
__global__ void prep_kernel(const float4* __restrict__ x,
                            const int4* __restrict__ codes,
                            const float* __restrict__ qgrid) {
    int b = blockIdx.x;
    if (b < X_BLOCKS) {
        // x: 8388608 float4, 8192 blocks * 256 thr * 4 each
        int base = b * 256 + threadIdx.x;
#pragma unroll
        for (int j = 0; j < 4; ++j) {
            int i = base + j * (X_BLOCKS * 256);
            float4 v = x[i];
            union U { __half h[4]; uint2 u; } H;
            H.h[0] = __float2half_rn(v.x);
            H.h[1] = __float2half_rn(v.y);
            H.h[2] = __float2half_rn(v.z);
            H.h[3] = __float2half_rn(v.w);
            reinterpret_cast<uint2*>(g_x)[i] = H.u;
        }
    } else {
        // w: 4194304 int4, 4096 blocks * 256 thr * 4 each
        int base = (b - X_BLOCKS) * 256 + threadIdx.x;
#pragma unroll
        for (int j = 0; j < 4; ++j) {
            int i = base + j * (W_BLOCKS * 256);
            int4 c = codes[i];
            int o = i >> 10;                  // (4*i) / 4096 : output row
            const float* g = qgrid + o * 8;   // GROUPS=1, GRID=8
            union U { __half h[4]; uint2 u; } H;
            H.h[0] = __float2half_rn(g[c.x]);
            H.h[1] = __float2half_rn(g[c.y]);
            H.h[2] = __float2half_rn(g[c.z]);
            H.h[3] = __float2half_rn(g[c.w]);
            reinterpret_cast<uint2*>(g_w)[i] = H.u;
        }
    }
}

// ============================================================
// GEMM: out[8192,4096] = x @ w^T   (fp16 in, fp32 acc)
// CTA 128x128, 4 warps (2 along M x 2 along N), warp tile 64x64.
// 3-stage cp.async pipeline, K chunk 64, 2 CTAs per SM.
// ============================================================
__global__ void __launch_bounds__(NTHREADS, 2)
gemm_kernel(float* __restrict__ out)
{
    extern __shared__ char dsm[];
    const uint32_t smem = (uint32_t)__cvta_generic_to_shared(dsm);
    const int tid  = threadIdx.x;
    const int wid  = tid >> 5;
    const int lane = tid & 31;
    const int m0 = blockIdx.y * CTA_M;
    const int n0 = blockIdx.x * CTA_N;
    const int warp_m = wid >> 1;          // 0..1 -> M offset *64
    const int warp_n = wid & 1;           // 0..1 -> N offset *64

    // ---------------- async load machinery ----------------
    // per stage: [0, XT_B) x tile (128 x 128B), [XT_B, STAGE_B) w (128 x 128B)
    auto load_chunk = [&](int it) {
        const uint32_t sb = smem + (uint32_t)(it % STAGES) * STAGE_B;
        const int k0 = it * KC;
        // x: 1024 16B-chunks, 8 per thread
#pragma unroll
        for (int j = 0; j < 8; ++j) {
            int id = tid + NTHREADS * j;   // 0..1023
            uint32_t r = id >> 3, c = id & 7;
            const char* gp = reinterpret_cast<const char*>(
                g_x + (size_t)(m0 + r) * IN_DIM + k0) + c * 16;
            CP_ASYNC16(sb + sw(r, c), gp);
        }
        // w: 1024 chunks, 8 per thread
#pragma unroll
        for (int j = 0; j < 8; ++j) {
            int id = tid + NTHREADS * j;
            uint32_t r = id >> 3, c = id & 7;
            const char* gp = reinterpret_cast<const char*>(
                g_w + (size_t)(n0 + r) * IN_DIM + k0) + c * 16;
            CP_ASYNC16(sb + XT_B + sw(r, c), gp);
        }
        CP_COMMIT();
    };

    float acc[4][8][4];
#pragma unroll
    for (int a = 0; a < 4; ++a)
#pragma unroll
        for (int b = 0; b < 8; ++b)
#pragma unroll
            for (int q = 0; q < 4; ++q) acc[a][b][q] = 0.f;

    // per-thread ldmatrix row/col components (x4 pattern)
    const uint32_t lrow = lane & 15;          // row within 16-row block
    const uint32_t lcol = lane >> 4;          // 0/1 -> +8 halves (16B col)
    const uint32_t arow = warp_m * 64 + lrow; // x tile row
    const uint32_t brow_base = warp_n * 64 + lrow;

    load_chunk(0);
    load_chunk(1);

    for (int it = 0; it < NUM_IT; ++it) {
        if (it < NUM_IT - 1) CP_WAIT1(); else CP_WAIT0();
        __syncthreads();
        if (it + 2 < NUM_IT) load_chunk(it + 2);

        const uint32_t sb = smem + (uint32_t)(it % STAGES) * STAGE_B;
        const uint32_t sx = sb;
        const uint32_t swt = sb + XT_B;

#pragma unroll
        for (int ks = 0; ks < 4; ++ks) {        // 4 x k16 per chunk
            const uint32_t cc = (uint32_t)(2 * ks) + lcol;   // 16B col index
            // B frags: 4 x ldmatrix.x4 covering 8 n8-tiles (64 N)
            uint32_t Bf[8][2];
#pragma unroll
            for (int np = 0; np < 4; ++np) {
                uint32_t r4[4];
                ldsm_x4(r4, swt + sw(brow_base + np * 16, cc));
                Bf[2 * np    ][0] = r4[0]; Bf[2 * np    ][1] = r4[2];
                Bf[2 * np + 1][0] = r4[1]; Bf[2 * np + 1][1] = r4[3];
            }
#pragma unroll
            for (int mt = 0; mt < 4; ++mt) {
                uint32_t Af[4];
                ldsm_x4(Af, sx + sw(arow + mt * 16, cc));
#pragma unroll
                for (int nt = 0; nt < 8; ++nt)
                    mma16816(acc[mt][nt], Af, Bf[nt]);
            }
        }
    }

    // ---------------- epilogue: direct fp32 stores ----------------
    const int orow = m0 + warp_m * 64 + (lane >> 2);
    const int ocol = n0 + warp_n * 64 + (lane & 3) * 2;
#pragma unroll
    for (int mt = 0; mt < 4; ++mt) {
#pragma unroll
        for (int nt = 0; nt < 8; ++nt) {
            float* p0 = out + (size_t)(orow + mt * 16) * OUT_DIM + ocol + nt * 8;
            float* p1 = out + (size_t)(orow + mt * 16 + 8) * OUT_DIM + ocol + nt * 8;
            *reinterpret_cast<float2*>(p0) =
                make_float2(acc[mt][nt][0], acc[mt][nt][1]);
            *reinterpret_cast<float2*>(p1) =
                make_float2(acc[mt][nt][2], acc[mt][nt][3]);
        }
    }
}

// ============================================================
// Launch
// ============================================================
extern "C" void kernel_launch(void* const* d_in, const int* in_sizes, int n_in,
                              void* d_out, int out_size) {
    // Identify inputs by element count:
    //   x: 33554432 fp32, quant_grid: 32768 fp32, weight_codes: 16777216 int32
    const float* x = nullptr;
    const float* qgrid = nullptr;
    const int* codes = nullptr;
    for (int i = 0; i < n_in; ++i) {
        if (in_sizes[i] == 33554432)      x = (const float*)d_in[i];
        else if (in_sizes[i] == 32768)    qgrid = (const float*)d_in[i];
        else if (in_sizes[i] == 16777216) codes = (const int*)d_in[i];
    }
    float* out = (float*)d_out;

    prep_kernel<<<X_BLOCKS + W_BLOCKS, 256>>>(
        reinterpret_cast<const float4*>(x),
        reinterpret_cast<const int4*>(codes), qgrid);

    cudaFuncSetAttribute(gemm_kernel,
                         cudaFuncAttributeMaxDynamicSharedMemorySize, SMEM_BYTES);
    dim3 grid(OUT_DIM / CTA_N, B_S / CTA_M);   // x = N blocks (fast), y = M
    gemm_kernel<<<grid, NTHREADS, SMEM_BYTES>>>(out);
}